// round 13
// baseline (speedup 1.0000x reference)
#include <cuda_runtime.h>
#include <cuda_fp16.h>
#include <math.h>
#include <stdint.h>

#define BB   2
#define CIN  16
#define NG   6
#define CG   16
#define NOC  96
#define TT   31
#define HH   128
#define WW   128
#define HWSZ (HH*WW)

// CTA: 8h x 16w output pixels = 4x8 = 32 Winograd tiles (2x2 out each)
#define NTHR 384          // 12 warps: wm = wid&1 (16 tiles), wn = wid>>1 (16 oc)

// smem layout (dynamic), occ 1:
//   halo [3dt][10][18][16ci] fp16          : 17280 B
//   V^   [16pt][32 tile][56 k]             : 57344 B (48 real k)
//   W^s  [16pt][2 chunk][96 oc][48 B]      : 147456 B (full Winograd weights)
#define HALO_BYTES (3*10*18*16*2)
#define VS_OFF   HALO_BYTES
#define VROW     112
#define VS_BYTES (16*32*VROW)
#define WS_OFF   (VS_OFF + VS_BYTES)         // 74624
#define WS_BYTES (16*2*96*48)                // 147456
#define SMEM_DYN (WS_OFF + WS_BYTES)         // 222080

// gates scratch [g][b][c][t][h][w]
__device__ float g_gates[(size_t)NG * BB * CG * TT * HWSZ];
// Winograd weights U = G g G^T : [pt=16][oc=96][48 k] fp16 (k = dt*16+ci)
__device__ __align__(16) __half g_wW[16 * NOC * 48];

// ---------------- helpers ----------------
__device__ __forceinline__ uint32_t smem_u32(const void* p) {
    uint32_t a;
    asm("{ .reg .u64 t; cvta.to.shared.u64 t, %1; cvt.u32.u64 %0, t; }"
        : "=r"(a) : "l"(p));
    return a;
}
__device__ __forceinline__ float ex2f(float z) {
    float r; asm("ex2.approx.f32 %0, %1;" : "=f"(r) : "f"(z)); return r;
}
__device__ __forceinline__ float rcpn(float d) {
    float r; asm("rcp.approx.f32 %0, %1;" : "=f"(r) : "f"(d));
    return r * fmaf(-d, r, 2.0f);
}
__device__ __forceinline__ float sigf(float v) {
    v = fminf(fmaxf(v, -80.f), 80.f);
    return rcpn(1.0f + ex2f(-1.442695041f * v));
}
__device__ __forceinline__ float tanhfst(float v) {
    v = fminf(fmaxf(v, -40.f), 40.f);
    return fmaf(2.0f, rcpn(1.0f + ex2f(-2.885390082f * v)), -1.0f);
}
__device__ __forceinline__ float2 f2add(float2 a, float2 b) {
    return make_float2(a.x + b.x, a.y + b.y);
}
__device__ __forceinline__ float2 f2sub(float2 a, float2 b) {
    return make_float2(a.x - b.x, a.y - b.y);
}

#define MMA_F16(c, a0, a1, a2, a3, b0, b1)                                    \
    asm volatile("mma.sync.aligned.m16n8k16.row.col.f32.f16.f16.f32 "         \
                 "{%0,%1,%2,%3}, {%4,%5,%6,%7}, {%8,%9}, {%0,%1,%2,%3};"      \
                 : "+f"((c)[0]), "+f"((c)[1]), "+f"((c)[2]), "+f"((c)[3])     \
                 : "r"(a0), "r"(a1), "r"(a2), "r"(a3), "r"(b0), "r"(b1))

#define LDSM_X4(r0, r1, r2, r3, addr)                                         \
    asm volatile("ldmatrix.sync.aligned.m8n8.x4.shared.b16 {%0,%1,%2,%3}, [%4];" \
                 : "=r"(r0), "=r"(r1), "=r"(r2), "=r"(r3) : "r"(addr))

// ---------------- weight prep: U = G g G^T, fp16, [pt][oc][48] ----------------
__global__ void prep_w(const float* __restrict__ cw)
{
    int idx = blockIdx.x * 256 + threadIdx.x;        // [0, 16*96*48)
    if (idx >= 16 * NOC * 48) return;
    int k  = idx % 48;
    int oc = (idx / 48) % NOC;
    int pt = idx / (48 * NOC);
    int ci = k & 15, dt = k >> 4;
    int xi = pt >> 2, nu = pt & 3;

    const float Gm[4][3] = {{1.f,0.f,0.f},{0.5f,0.5f,0.5f},
                            {0.5f,-0.5f,0.5f},{0.f,0.f,1.f}};
    const float* g = cw + ((size_t)oc * CIN + ci) * 27 + dt * 9;
    float u = 0.f;
#pragma unroll
    for (int dh = 0; dh < 3; dh++)
#pragma unroll
        for (int dw = 0; dw < 3; dw++)
            u += Gm[xi][dh] * Gm[nu][dw] * g[dh * 3 + dw];
    g_wW[((size_t)pt * NOC + oc) * 48 + k] = __float2half_rn(u);
}

// ---------------- conv: Winograd F(2x2,3x3), fp16 mma, full-W^ smem --------
__global__ __launch_bounds__(NTHR, 1)
void conv_wino(const float* __restrict__ x, const float* __restrict__ cb)
{
    extern __shared__ __align__(16) char dsm[];
    __shared__ float cbs[NOC];

    const int tid = threadIdx.x;
    const int wid = tid >> 5;
    const int lid = tid & 31;
    const int wm  = wid & 1;          // m-group: 16 tiles
    const int wn  = wid >> 1;         // n-group: 16 oc (== gate index!)

    const int w0 = blockIdx.x * 16;
    const int h0 = blockIdx.y * 8;
    const int zz = blockIdx.z;
    const int t = zz % TT, b = zz / TT;

    const uint32_t sbase = smem_u32(dsm);

    if (tid < NOC) cbs[tid] = __ldg(&cb[tid]);

    // ---- stage full W^ into smem, re-chunked [pt][chunk2][oc][48B] ----
    // src g_wW: [pt][oc][96B row]; unit u = 16B: u = (pt*96 + oc)*6 + j
    // logical byte off j*16 -> chunk = j/3, rem = (j%3)*16
    {
        const uint4* wsrc = (const uint4*)g_wW;
        for (int u = tid; u < 16 * NOC * 6; u += NTHR) {
            uint4 v = __ldg(&wsrc[u]);
            int j   = u % 6;
            int oc  = (u / 6) % NOC;
            int pt  = u / (6 * NOC);
            int chunk = j / 3, rem = (j % 3) * 16;
            *(uint4*)(dsm + WS_OFF + pt * 9216 + chunk * 4608 + oc * 48 + rem) = v;
        }
    }

    // ---- stage halo [3][10][18][16] fp16 (h0-1..h0+8, w0-1..w0+16) ----
    {
        const float* xb = x + (size_t)b * CIN * TT * HWSZ;
        for (int i = tid; i < 3 * 10 * 18 * CIN; i += NTHR) {
            int iw  = i % 18;
            int ih  = (i / 18) % 10;
            int ci  = (i / 180) % CIN;
            int dtt = i / 2880;
            int tg = t - 1 + dtt, hh = h0 - 1 + ih, ww = w0 - 1 + iw;
            float v = 0.0f;
            if ((unsigned)tg < TT && (unsigned)hh < HH && (unsigned)ww < WW)
                v = xb[((size_t)ci * TT + tg) * HWSZ + hh * WW + ww];
            *(__half*)(dsm + (((dtt * 10 + ih) * 18 + iw) * 16 + ci) * 2)
                = __float2half_rn(v);
        }
    }
    __syncthreads();

    // ---- input transform: V^[pt][tile][k], f32 math ----
#pragma unroll
    for (int rep = 0; rep < 2; rep++) {
        const int it  = tid + rep * NTHR;
        const int cp  = it & 7;
        const int tl  = (it >> 3) & 31;
        const int dtt = it >> 8;
        const int th_ = tl >> 3, tw_ = tl & 7;

        float2 d[4][4];
#pragma unroll
        for (int i = 0; i < 4; i++)
#pragma unroll
            for (int j = 0; j < 4; j++) {
                uint32_t h2 = *(const uint32_t*)(dsm +
                    (((dtt * 10 + 2 * th_ + i) * 18 + 2 * tw_ + j) * 16
                     + cp * 2) * 2);
                d[i][j] = __half22float2(*(const __half2*)&h2);
            }
        float2 tr[4][4];
#pragma unroll
        for (int j = 0; j < 4; j++) {
            tr[0][j] = f2sub(d[0][j], d[2][j]);
            tr[1][j] = f2add(d[1][j], d[2][j]);
            tr[2][j] = f2sub(d[2][j], d[1][j]);
            tr[3][j] = f2sub(d[1][j], d[3][j]);
        }
#pragma unroll
        for (int i = 0; i < 4; i++) {
            float2 v0 = f2sub(tr[i][0], tr[i][2]);
            float2 v1 = f2add(tr[i][1], tr[i][2]);
            float2 v2 = f2sub(tr[i][2], tr[i][1]);
            float2 v3 = f2sub(tr[i][1], tr[i][3]);
            float2 vv[4] = {v0, v1, v2, v3};
#pragma unroll
            for (int j = 0; j < 4; j++) {
                __half2 hv = __float22half2_rn(vv[j]);
                *(__half2*)(dsm + VS_OFF + ((i * 4 + j) * 32 + tl) * VROW
                            + dtt * 32 + cp * 4) = hv;
            }
        }
    }

    // ---- Y accumulators (2x2 out px per tile), init with bias ----
    float y[2][2][2][2][2];   // [ti][nf][par][py][px]
    {
        const int q = lid & 3;
#pragma unroll
        for (int nf = 0; nf < 2; nf++)
#pragma unroll
            for (int par = 0; par < 2; par++) {
                float bv = cbs[wn * 16 + nf * 8 + q * 2 + par];
#pragma unroll
                for (int ti = 0; ti < 2; ti++) {
                    y[ti][nf][par][0][0] = bv; y[ti][nf][par][0][1] = bv;
                    y[ti][nf][par][1][0] = bv; y[ti][nf][par][1][1] = bv;
                }
            }
    }
    __syncthreads();   // V^ + W^s fully built; loop below is barrier-free

    // A fragment lane address (LDSM from V^)
    const int aRow  = (lid & 7) + 8 * ((lid >> 3) & 1);
    const int aKoff = ((lid >> 4) & 1) * 16;
    const uint32_t laneA = sbase + VS_OFF
        + (uint32_t)((wm * 16 + aRow) * VROW + aKoff);

    // B fragment lane address (LDSM from W^s chunked rows, 48B stride)
    const uint32_t hb = (lid >> 4) & 1;
    const uint32_t laneB0 = sbase + WS_OFF
        + (uint32_t)((wn * 16 + (lid & 15)) * 48);
    // per-kk lane offsets into [chunk2][..] layout:
    //  kk0: hb0->0,   hb1->16 ;  kk1: hb0->32, hb1->4608 ; kk2: 4624/4640
    const uint32_t bOff0 = hb * 16u;
    const uint32_t bOff1 = hb ? 4608u : 32u;
    const uint32_t bOff2 = 4624u + hb * 16u;

    const int AT[2][4] = {{1, 1, 1, 0}, {0, 1, -1, -1}};

#pragma unroll
    for (int pt = 0; pt < 16; pt++) {
        float c[2][4];
        c[0][0]=0;c[0][1]=0;c[0][2]=0;c[0][3]=0;
        c[1][0]=0;c[1][1]=0;c[1][2]=0;c[1][3]=0;

        const uint32_t va = laneA + (uint32_t)(pt * 32 * VROW);
        const uint32_t wa = laneB0 + (uint32_t)(pt * 9216);
        {
            uint32_t a0, a1, a2, a3, r0, r1, r2, r3;
            LDSM_X4(a0, a1, a2, a3, va);
            LDSM_X4(r0, r1, r2, r3, wa + bOff0);
            MMA_F16(c[0], a0, a1, a2, a3, r0, r2);
            MMA_F16(c[1], a0, a1, a2, a3, r1, r3);
            LDSM_X4(a0, a1, a2, a3, va + 32);
            LDSM_X4(r0, r1, r2, r3, wa + bOff1);
            MMA_F16(c[0], a0, a1, a2, a3, r0, r2);
            MMA_F16(c[1], a0, a1, a2, a3, r1, r3);
            LDSM_X4(a0, a1, a2, a3, va + 64);
            LDSM_X4(r0, r1, r2, r3, wa + bOff2);
            MMA_F16(c[0], a0, a1, a2, a3, r0, r2);
            MMA_F16(c[1], a0, a1, a2, a3, r1, r3);
        }

        // accumulate into Y with A^T coeffs (compile-time after unroll)
        const int xi = pt >> 2, nu = pt & 3;
#pragma unroll
        for (int ti = 0; ti < 2; ti++)
#pragma unroll
            for (int nf = 0; nf < 2; nf++)
#pragma unroll
                for (int par = 0; par < 2; par++) {
                    float v = c[nf][par + 2 * ti];
#pragma unroll
                    for (int py = 0; py < 2; py++) {
                        int ay = AT[py][xi];
                        if (ay == 0) continue;
#pragma unroll
                        for (int px = 0; px < 2; px++) {
                            int ax = AT[px][nu];
                            if (ax == 0) continue;
                            if (ay * ax > 0) y[ti][nf][par][py][px] += v;
                            else            y[ti][nf][par][py][px] -= v;
                        }
                    }
                }
    }

    // ---- epilogue: activate + store 2x2 px per (tile, oc) ----
    {
        const int r = lid >> 2, q = lid & 3;
        const bool th = (wn == 0) || (wn == 5);
        const size_t tbase = (size_t)t * HWSZ;
#pragma unroll
        for (int ti = 0; ti < 2; ti++) {
            const int tl  = wm * 16 + r + 8 * ti;
            const int hA  = h0 + 2 * (tl >> 3);
            const int wA  = w0 + 2 * (tl & 7);
#pragma unroll
            for (int nf = 0; nf < 2; nf++)
#pragma unroll
                for (int par = 0; par < 2; par++) {
                    const int ocl = nf * 8 + q * 2 + par;
                    float* bp = g_gates
                        + ((size_t)(wn * BB + b) * CG + ocl) * (TT * HWSZ)
                        + tbase;
#pragma unroll
                    for (int py = 0; py < 2; py++) {
                        float v0 = y[ti][nf][par][py][0];
                        float v1 = y[ti][nf][par][py][1];
                        v0 = th ? tanhfst(v0) : sigf(v0);
                        v1 = th ? tanhfst(v1) : sigf(v1);
                        *(float2*)(bp + (size_t)(hA + py) * WW + wA)
                            = make_float2(v0, v1);
                    }
                }
        }
    }
}

// ---------------- SRU scan (HBM-bound @80%, unchanged) ----------------
__global__ __launch_bounds__(256)
void sru_scan_kernel(float* __restrict__ out)
{
    const int tid = blockIdx.x * blockDim.x + threadIdx.x;
    const int hw = tid & (HWSZ - 1);
    const int bc = tid >> 14;
    const int c  = bc & 15;
    const int b  = bc >> 4;

    const size_t GSZ  = (size_t)BB * CG * TT * HWSZ;
    const size_t base = (((size_t)b * CG + c) * TT) * HWSZ + hw;

    const float* WX  = g_gates + 0 * GSZ + base;
    const float* FT  = g_gates + 1 * GSZ + base;
    const float* FT2 = g_gates + 2 * GSZ + base;
    const float* RT  = g_gates + 3 * GSZ + base;
    const float* RT2 = g_gates + 4 * GSZ + base;
    const float* XX  = g_gates + 5 * GSZ + base;
    float* o = out + base;

    float htl[TT];
    {
        float f = FT[0];
        float C = 1.0f - f;
        float r = RT[0];
        htl[0] = r * C + (1.0f - r) * XX[0];
#pragma unroll
        for (int t = 1; t < TT; t++) {
            size_t idx = (size_t)t * HWSZ;
            f = FT[idx];
            C = f * C + (1.0f - f) * WX[idx];
            float r2 = RT[idx];
            htl[t] = r2 * C + (1.0f - r2) * XX[idx];
        }
    }
    {
        size_t idx = (size_t)(TT - 1) * HWSZ;
        float f = FT2[idx];
        float C = 1.0f - f;
        float r = RT2[idx];
        o[idx] = htl[TT - 1] + r * C + (1.0f - r) * XX[idx];
#pragma unroll
        for (int t = TT - 2; t >= 0; t--) {
            idx = (size_t)t * HWSZ;
            f = FT2[idx];
            C = f * C + (1.0f - f) * WX[idx];
            float r2 = RT2[idx];
            o[idx] = htl[t] + r2 * C + (1.0f - r2) * XX[idx];
        }
    }
}

extern "C" void kernel_launch(void* const* d_in, const int* in_sizes, int n_in,
                              void* d_out, int out_size)
{
    const float* x  = (const float*)d_in[0];   // [2,16,31,128,128]
    const float* cw = (const float*)d_in[1];   // [96,16,3,3,3]
    const float* cb = (const float*)d_in[2];   // [96]
    float* out = (float*)d_out;

    cudaFuncSetAttribute(conv_wino, cudaFuncAttributeMaxDynamicSharedMemorySize,
                         SMEM_DYN);

    prep_w<<<(16 * NOC * 48 + 255) / 256, 256>>>(cw);

    dim3 grd(WW / 16, HH / 8, BB * TT);        // (8, 16, 62) = 7936 CTAs
    conv_wino<<<grd, NTHR, SMEM_DYN>>>(x, cb);

    int n = BB * CG * HWSZ;
    sru_scan_kernel<<<n / 256, 256>>>(out);
}

// round 14
// speedup vs baseline: 1.4133x; 1.4133x over previous
#include <cuda_runtime.h>
#include <cuda_fp16.h>
#include <math.h>
#include <stdint.h>

#define BB   2
#define CIN  16
#define NG   6
#define CG   16
#define NOC  96
#define TT   31
#define HH   128
#define WW   128
#define HWSZ (HH*WW)

// CTA: 8h x 16w output pixels = 4x8 = 32 Winograd tiles (2x2 out each)
#define NTHR 384          // 12 warps: each warp = ALL 32 tiles x 8 oc (oc = wid*8..+8)

// smem layout (dynamic):
//   halo [3dt][10][18][16ci] fp16 : 17280 B
//   V^   [16pt][32 tile][56 k]    : 57344 B (48 real k)
#define HALO_BYTES (3*10*18*16*2)
#define VS_OFF   HALO_BYTES
#define VROW     112
#define VS_BYTES (16*32*VROW)
#define SMEM_DYN (VS_OFF + VS_BYTES)   // 74624  -> 2 CTAs/SM

// gates scratch [g][b][c][t][h][w]
__device__ float g_gates[(size_t)NG * BB * CG * TT * HWSZ];
// Winograd weights U = G g G^T : [pt=16][oc=96][48 k] fp16 (k = dt*16+ci)
__device__ __align__(16) __half g_wW[16 * NOC * 48];

// ---------------- helpers ----------------
__device__ __forceinline__ uint32_t smem_u32(const void* p) {
    uint32_t a;
    asm("{ .reg .u64 t; cvta.to.shared.u64 t, %1; cvt.u32.u64 %0, t; }"
        : "=r"(a) : "l"(p));
    return a;
}
__device__ __forceinline__ float ex2f(float z) {
    float r; asm("ex2.approx.f32 %0, %1;" : "=f"(r) : "f"(z)); return r;
}
__device__ __forceinline__ float rcpn(float d) {
    float r; asm("rcp.approx.f32 %0, %1;" : "=f"(r) : "f"(d));
    return r * fmaf(-d, r, 2.0f);
}
__device__ __forceinline__ float sigf(float v) {
    v = fminf(fmaxf(v, -80.f), 80.f);
    return rcpn(1.0f + ex2f(-1.442695041f * v));
}
__device__ __forceinline__ float tanhfst(float v) {
    v = fminf(fmaxf(v, -40.f), 40.f);
    return fmaf(2.0f, rcpn(1.0f + ex2f(-2.885390082f * v)), -1.0f);
}
__device__ __forceinline__ float2 f2add(float2 a, float2 b) {
    return make_float2(a.x + b.x, a.y + b.y);
}
__device__ __forceinline__ float2 f2sub(float2 a, float2 b) {
    return make_float2(a.x - b.x, a.y - b.y);
}

#define MMA_F16(c, a0, a1, a2, a3, b0, b1)                                    \
    asm volatile("mma.sync.aligned.m16n8k16.row.col.f32.f16.f16.f32 "         \
                 "{%0,%1,%2,%3}, {%4,%5,%6,%7}, {%8,%9}, {%0,%1,%2,%3};"      \
                 : "+f"((c)[0]), "+f"((c)[1]), "+f"((c)[2]), "+f"((c)[3])     \
                 : "r"(a0), "r"(a1), "r"(a2), "r"(a3), "r"(b0), "r"(b1))

#define LDSM_X4(r0, r1, r2, r3, addr)                                         \
    asm volatile("ldmatrix.sync.aligned.m8n8.x4.shared.b16 {%0,%1,%2,%3}, [%4];" \
                 : "=r"(r0), "=r"(r1), "=r"(r2), "=r"(r3) : "r"(addr))

// ---------------- weight prep: U = G g G^T, fp16, [pt][oc][48] ----------------
__global__ void prep_w(const float* __restrict__ cw)
{
    int idx = blockIdx.x * 256 + threadIdx.x;        // [0, 16*96*48)
    if (idx >= 16 * NOC * 48) return;
    int k  = idx % 48;
    int oc = (idx / 48) % NOC;
    int pt = idx / (48 * NOC);
    int ci = k & 15, dt = k >> 4;
    int xi = pt >> 2, nu = pt & 3;

    const float Gm[4][3] = {{1.f,0.f,0.f},{0.5f,0.5f,0.5f},
                            {0.5f,-0.5f,0.5f},{0.f,0.f,1.f}};
    const float* g = cw + ((size_t)oc * CIN + ci) * 27 + dt * 9;
    float u = 0.f;
#pragma unroll
    for (int dh = 0; dh < 3; dh++)
#pragma unroll
        for (int dw = 0; dw < 3; dw++)
            u += Gm[xi][dh] * Gm[nu][dw] * g[dh * 3 + dw];
    g_wW[((size_t)pt * NOC + oc) * 48 + k] = __float2half_rn(u);
}

// ---------------- conv: Winograd F(2x2,3x3), M32xN8 warps, B prefetch ------
__global__ __launch_bounds__(NTHR, 2)
void conv_wino(const float* __restrict__ x, const float* __restrict__ cb)
{
    extern __shared__ __align__(16) char dsm[];
    __shared__ float cbs[NOC];

    const int tid = threadIdx.x;
    const int wid = tid >> 5;         // 0..11: oc slice = wid*8..wid*8+7
    const int lid = tid & 31;

    const int w0 = blockIdx.x * 16;
    const int h0 = blockIdx.y * 8;
    const int zz = blockIdx.z;
    const int t = zz % TT, b = zz / TT;

    const uint32_t sbase = smem_u32(dsm);

    if (tid < NOC) cbs[tid] = __ldg(&cb[tid]);

    // ---- stage halo [3][10][18][16] fp16 (h0-1..h0+8, w0-1..w0+16) ----
    {
        const float* xb = x + (size_t)b * CIN * TT * HWSZ;
        for (int i = tid; i < 3 * 10 * 18 * CIN; i += NTHR) {
            int iw  = i % 18;
            int ih  = (i / 18) % 10;
            int ci  = (i / 180) % CIN;
            int dtt = i / 2880;
            int tg = t - 1 + dtt, hh = h0 - 1 + ih, ww = w0 - 1 + iw;
            float v = 0.0f;
            if ((unsigned)tg < TT && (unsigned)hh < HH && (unsigned)ww < WW)
                v = xb[((size_t)ci * TT + tg) * HWSZ + hh * WW + ww];
            *(__half*)(dsm + (((dtt * 10 + ih) * 18 + iw) * 16 + ci) * 2)
                = __float2half_rn(v);
        }
    }
    __syncthreads();

    // ---- input transform: V^[pt][tile][k], f32 math ----
#pragma unroll
    for (int rep = 0; rep < 2; rep++) {
        const int it  = tid + rep * NTHR;
        const int cp  = it & 7;
        const int tl  = (it >> 3) & 31;
        const int dtt = it >> 8;
        const int th_ = tl >> 3, tw_ = tl & 7;

        float2 d[4][4];
#pragma unroll
        for (int i = 0; i < 4; i++)
#pragma unroll
            for (int j = 0; j < 4; j++) {
                uint32_t h2 = *(const uint32_t*)(dsm +
                    (((dtt * 10 + 2 * th_ + i) * 18 + 2 * tw_ + j) * 16
                     + cp * 2) * 2);
                d[i][j] = __half22float2(*(const __half2*)&h2);
            }
        float2 tr[4][4];
#pragma unroll
        for (int j = 0; j < 4; j++) {
            tr[0][j] = f2sub(d[0][j], d[2][j]);
            tr[1][j] = f2add(d[1][j], d[2][j]);
            tr[2][j] = f2sub(d[2][j], d[1][j]);
            tr[3][j] = f2sub(d[1][j], d[3][j]);
        }
#pragma unroll
        for (int i = 0; i < 4; i++) {
            float2 v0 = f2sub(tr[i][0], tr[i][2]);
            float2 v1 = f2add(tr[i][1], tr[i][2]);
            float2 v2 = f2sub(tr[i][2], tr[i][1]);
            float2 v3 = f2sub(tr[i][1], tr[i][3]);
            float2 vv[4] = {v0, v1, v2, v3};
#pragma unroll
            for (int j = 0; j < 4; j++) {
                __half2 hv = __float22half2_rn(vv[j]);
                *(__half2*)(dsm + VS_OFF + ((i * 4 + j) * 32 + tl) * VROW
                            + dtt * 32 + cp * 4) = hv;
            }
        }
    }

    // ---- Y accumulators: [mb][ti][par][py][px], init with bias ----
    float y[2][2][2][2][2];
    {
        const int q = lid & 3;
#pragma unroll
        for (int par = 0; par < 2; par++) {
            float bv = cbs[wid * 8 + q * 2 + par];
#pragma unroll
            for (int mb = 0; mb < 2; mb++)
#pragma unroll
                for (int ti = 0; ti < 2; ti++) {
                    y[mb][ti][par][0][0] = bv; y[mb][ti][par][0][1] = bv;
                    y[mb][ti][par][1][0] = bv; y[mb][ti][par][1][1] = bv;
                }
        }
    }
    __syncthreads();   // V^ fully built; loop below is barrier-free

    // A fragment lane addresses (LDSM from V^), two m16 tiles
    const int aRow  = (lid & 7) + 8 * ((lid >> 3) & 1);
    const int aKoff = ((lid >> 4) & 1) * 16;
    const uint32_t laneA0 = sbase + VS_OFF
        + (uint32_t)(aRow * VROW + aKoff);
    const uint32_t laneA1 = laneA0 + 16 * VROW;

    // B fragment lane gmem pointer: n = wid*8 + lid>>2, k = (lid&3)*2 (+8 for b1)
    const __half* wrow = g_wW + (size_t)(wid * 8 + (lid >> 2)) * 48
                       + (lid & 3) * 2;

    const int AT[2][4] = {{1, 1, 1, 0}, {0, 1, -1, -1}};

    // prefetch B for pt 0
    uint32_t bc[6];
    {
        const __half* w0p = wrow;
#pragma unroll
        for (int kk = 0; kk < 3; kk++) {
            bc[2 * kk]     = __ldg((const uint32_t*)(w0p + kk * 16));
            bc[2 * kk + 1] = __ldg((const uint32_t*)(w0p + kk * 16 + 8));
        }
    }

#pragma unroll
    for (int pt = 0; pt < 16; pt++) {
        // prefetch B for pt+1
        uint32_t bn[6];
        if (pt < 15) {
            const __half* wnp = wrow + (size_t)(pt + 1) * NOC * 48;
#pragma unroll
            for (int kk = 0; kk < 3; kk++) {
                bn[2 * kk]     = __ldg((const uint32_t*)(wnp + kk * 16));
                bn[2 * kk + 1] = __ldg((const uint32_t*)(wnp + kk * 16 + 8));
            }
        }

        float c[2][4];
        c[0][0]=0;c[0][1]=0;c[0][2]=0;c[0][3]=0;
        c[1][0]=0;c[1][1]=0;c[1][2]=0;c[1][3]=0;

        const uint32_t off = (uint32_t)(pt * 32 * VROW);
#pragma unroll
        for (int kk = 0; kk < 3; kk++) {
            uint32_t a0, a1, a2, a3;
            LDSM_X4(a0, a1, a2, a3, laneA0 + off + kk * 32);
            MMA_F16(c[0], a0, a1, a2, a3, bc[2 * kk], bc[2 * kk + 1]);
            LDSM_X4(a0, a1, a2, a3, laneA1 + off + kk * 32);
            MMA_F16(c[1], a0, a1, a2, a3, bc[2 * kk], bc[2 * kk + 1]);
        }

#pragma unroll
        for (int i = 0; i < 6; i++) bc[i] = bn[i];

        // accumulate into Y with A^T coeffs (compile-time after unroll)
        const int xi = pt >> 2, nu = pt & 3;
#pragma unroll
        for (int mb = 0; mb < 2; mb++)
#pragma unroll
            for (int ti = 0; ti < 2; ti++)
#pragma unroll
                for (int par = 0; par < 2; par++) {
                    float v = c[mb][par + 2 * ti];
#pragma unroll
                    for (int py = 0; py < 2; py++) {
                        int ay = AT[py][xi];
                        if (ay == 0) continue;
#pragma unroll
                        for (int px = 0; px < 2; px++) {
                            int ax = AT[px][nu];
                            if (ax == 0) continue;
                            if (ay * ax > 0) y[mb][ti][par][py][px] += v;
                            else            y[mb][ti][par][py][px] -= v;
                        }
                    }
                }
    }

    // ---- epilogue: activate + store 2x2 px per (tile, oc) ----
    {
        const int r = lid >> 2, q = lid & 3;
        const int g  = wid >> 1;               // gate = (wid*8)>>4
        const bool th = (g == 0) || (g == 5);
        const size_t tbase = (size_t)t * HWSZ;
#pragma unroll
        for (int mb = 0; mb < 2; mb++)
#pragma unroll
            for (int ti = 0; ti < 2; ti++) {
                const int tl  = mb * 16 + r + 8 * ti;
                const int hA  = h0 + 2 * (tl >> 3);
                const int wA  = w0 + 2 * (tl & 7);
#pragma unroll
                for (int par = 0; par < 2; par++) {
                    const int oc = wid * 8 + q * 2 + par;
                    float* bp = g_gates
                        + ((size_t)(g * BB + b) * CG + (oc & 15)) * (TT * HWSZ)
                        + tbase;
#pragma unroll
                    for (int py = 0; py < 2; py++) {
                        float v0 = y[mb][ti][par][py][0];
                        float v1 = y[mb][ti][par][py][1];
                        v0 = th ? tanhfst(v0) : sigf(v0);
                        v1 = th ? tanhfst(v1) : sigf(v1);
                        *(float2*)(bp + (size_t)(hA + py) * WW + wA)
                            = make_float2(v0, v1);
                    }
                }
            }
    }
}

// ---------------- SRU scan (HBM-bound @80%, unchanged) ----------------
__global__ __launch_bounds__(256)
void sru_scan_kernel(float* __restrict__ out)
{
    const int tid = blockIdx.x * blockDim.x + threadIdx.x;
    const int hw = tid & (HWSZ - 1);
    const int bc = tid >> 14;
    const int c  = bc & 15;
    const int b  = bc >> 4;

    const size_t GSZ  = (size_t)BB * CG * TT * HWSZ;
    const size_t base = (((size_t)b * CG + c) * TT) * HWSZ + hw;

    const float* WX  = g_gates + 0 * GSZ + base;
    const float* FT  = g_gates + 1 * GSZ + base;
    const float* FT2 = g_gates + 2 * GSZ + base;
    const float* RT  = g_gates + 3 * GSZ + base;
    const float* RT2 = g_gates + 4 * GSZ + base;
    const float* XX  = g_gates + 5 * GSZ + base;
    float* o = out + base;

    float htl[TT];
    {
        float f = FT[0];
        float C = 1.0f - f;
        float r = RT[0];
        htl[0] = r * C + (1.0f - r) * XX[0];
#pragma unroll
        for (int t = 1; t < TT; t++) {
            size_t idx = (size_t)t * HWSZ;
            f = FT[idx];
            C = f * C + (1.0f - f) * WX[idx];
            float r2 = RT[idx];
            htl[t] = r2 * C + (1.0f - r2) * XX[idx];
        }
    }
    {
        size_t idx = (size_t)(TT - 1) * HWSZ;
        float f = FT2[idx];
        float C = 1.0f - f;
        float r = RT2[idx];
        o[idx] = htl[TT - 1] + r * C + (1.0f - r) * XX[idx];
#pragma unroll
        for (int t = TT - 2; t >= 0; t--) {
            idx = (size_t)t * HWSZ;
            f = FT2[idx];
            C = f * C + (1.0f - f) * WX[idx];
            float r2 = RT2[idx];
            o[idx] = htl[t] + r2 * C + (1.0f - r2) * XX[idx];
        }
    }
}

extern "C" void kernel_launch(void* const* d_in, const int* in_sizes, int n_in,
                              void* d_out, int out_size)
{
    const float* x  = (const float*)d_in[0];   // [2,16,31,128,128]
    const float* cw = (const float*)d_in[1];   // [96,16,3,3,3]
    const float* cb = (const float*)d_in[2];   // [96]
    float* out = (float*)d_out;

    cudaFuncSetAttribute(conv_wino, cudaFuncAttributeMaxDynamicSharedMemorySize,
                         SMEM_DYN);

    prep_w<<<(16 * NOC * 48 + 255) / 256, 256>>>(cw);

    dim3 grd(WW / 16, HH / 8, BB * TT);        // (8, 16, 62) = 7936 CTAs
    conv_wino<<<grd, NTHR, SMEM_DYN>>>(x, cb);

    int n = BB * CG * HWSZ;
    sru_scan_kernel<<<n / 256, 256>>>(out);
}

// round 15
// speedup vs baseline: 1.4530x; 1.0281x over previous
#include <cuda_runtime.h>
#include <cuda_fp16.h>
#include <math.h>
#include <stdint.h>

#define BB   2
#define CIN  16
#define NG   6
#define CG   16
#define NOC  96
#define TT   31
#define HH   128
#define WW   128
#define HWSZ (HH*WW)

// CTA: 8h x 16w output pixels = 4x8 = 32 Winograd tiles (2x2 out each)
#define NTHR 384          // 12 warps: each warp = ALL 32 tiles x 8 oc (oc = wid*8..+8)

// smem layout (dynamic):
//   halo [3dt][10][18][16ci] fp16 : 17280 B
//   V^   [16pt][32 tile][56 k]    : 57344 B (48 real k)
#define HALO_BYTES (3*10*18*16*2)
#define VS_OFF   HALO_BYTES
#define VROW     112
#define VS_BYTES (16*32*VROW)
#define SMEM_DYN (VS_OFF + VS_BYTES)   // 74624  -> 3 CTAs/SM

// gates scratch [g][b][c][t][h][w]
__device__ float g_gates[(size_t)NG * BB * CG * TT * HWSZ];
// Winograd weights U = G g G^T : [pt=16][oc=96][48 k] fp16 (k = dt*16+ci)
__device__ __align__(16) __half g_wW[16 * NOC * 48];

// ---------------- helpers ----------------
__device__ __forceinline__ uint32_t smem_u32(const void* p) {
    uint32_t a;
    asm("{ .reg .u64 t; cvta.to.shared.u64 t, %1; cvt.u32.u64 %0, t; }"
        : "=r"(a) : "l"(p));
    return a;
}
__device__ __forceinline__ float ex2f(float z) {
    float r; asm("ex2.approx.f32 %0, %1;" : "=f"(r) : "f"(z)); return r;
}
__device__ __forceinline__ float rcpn(float d) {
    float r; asm("rcp.approx.f32 %0, %1;" : "=f"(r) : "f"(d));
    return r * fmaf(-d, r, 2.0f);
}
__device__ __forceinline__ float sigf(float v) {
    v = fminf(fmaxf(v, -80.f), 80.f);
    return rcpn(1.0f + ex2f(-1.442695041f * v));
}
__device__ __forceinline__ float tanhfst(float v) {
    v = fminf(fmaxf(v, -40.f), 40.f);
    return fmaf(2.0f, rcpn(1.0f + ex2f(-2.885390082f * v)), -1.0f);
}
__device__ __forceinline__ float2 f2add(float2 a, float2 b) {
    return make_float2(a.x + b.x, a.y + b.y);
}
__device__ __forceinline__ float2 f2sub(float2 a, float2 b) {
    return make_float2(a.x - b.x, a.y - b.y);
}

#define MMA_F16(c, a0, a1, a2, a3, b0, b1)                                    \
    asm volatile("mma.sync.aligned.m16n8k16.row.col.f32.f16.f16.f32 "         \
                 "{%0,%1,%2,%3}, {%4,%5,%6,%7}, {%8,%9}, {%0,%1,%2,%3};"      \
                 : "+f"((c)[0]), "+f"((c)[1]), "+f"((c)[2]), "+f"((c)[3])     \
                 : "r"(a0), "r"(a1), "r"(a2), "r"(a3), "r"(b0), "r"(b1))

#define LDSM_X4(r0, r1, r2, r3, addr)                                         \
    asm volatile("ldmatrix.sync.aligned.m8n8.x4.shared.b16 {%0,%1,%2,%3}, [%4];" \
                 : "=r"(r0), "=r"(r1), "=r"(r2), "=r"(r3) : "r"(addr))

// ---------------- weight prep: U = G g G^T, fp16, [pt][oc][48] ----------------
__global__ void prep_w(const float* __restrict__ cw)
{
    int idx = blockIdx.x * 256 + threadIdx.x;        // [0, 16*96*48)
    if (idx >= 16 * NOC * 48) return;
    int k  = idx % 48;
    int oc = (idx / 48) % NOC;
    int pt = idx / (48 * NOC);
    int ci = k & 15, dt = k >> 4;
    int xi = pt >> 2, nu = pt & 3;

    const float Gm[4][3] = {{1.f,0.f,0.f},{0.5f,0.5f,0.5f},
                            {0.5f,-0.5f,0.5f},{0.f,0.f,1.f}};
    const float* g = cw + ((size_t)oc * CIN + ci) * 27 + dt * 9;
    float u = 0.f;
#pragma unroll
    for (int dh = 0; dh < 3; dh++)
#pragma unroll
        for (int dw = 0; dw < 3; dw++)
            u += Gm[xi][dh] * Gm[nu][dw] * g[dh * 3 + dw];
    g_wW[((size_t)pt * NOC + oc) * 48 + k] = __float2half_rn(u);
}

// ---------------- conv: Winograd F(2x2,3x3), M32xN8 warps, occ 3 -----------
__global__ __launch_bounds__(NTHR, 3)
void conv_wino(const float* __restrict__ x, const float* __restrict__ cb)
{
    extern __shared__ __align__(16) char dsm[];
    __shared__ float cbs[NOC];

    const int tid = threadIdx.x;
    const int wid = tid >> 5;         // 0..11: oc slice = wid*8..wid*8+7
    const int lid = tid & 31;

    const int w0 = blockIdx.x * 16;
    const int h0 = blockIdx.y * 8;
    const int zz = blockIdx.z;
    const int t = zz % TT, b = zz / TT;

    const uint32_t sbase = smem_u32(dsm);

    if (tid < NOC) cbs[tid] = __ldg(&cb[tid]);

    // ---- stage halo [3][10][18][16] fp16 (h0-1..h0+8, w0-1..w0+16) ----
    {
        const float* xb = x + (size_t)b * CIN * TT * HWSZ;
        for (int i = tid; i < 3 * 10 * 18 * CIN; i += NTHR) {
            int iw  = i % 18;
            int ih  = (i / 18) % 10;
            int ci  = (i / 180) % CIN;
            int dtt = i / 2880;
            int tg = t - 1 + dtt, hh = h0 - 1 + ih, ww = w0 - 1 + iw;
            float v = 0.0f;
            if ((unsigned)tg < TT && (unsigned)hh < HH && (unsigned)ww < WW)
                v = xb[((size_t)ci * TT + tg) * HWSZ + hh * WW + ww];
            *(__half*)(dsm + (((dtt * 10 + ih) * 18 + iw) * 16 + ci) * 2)
                = __float2half_rn(v);
        }
    }
    __syncthreads();

    // ---- input transform: V^[pt][tile][k], f32 math ----
#pragma unroll
    for (int rep = 0; rep < 2; rep++) {
        const int it  = tid + rep * NTHR;
        const int cp  = it & 7;
        const int tl  = (it >> 3) & 31;
        const int dtt = it >> 8;
        const int th_ = tl >> 3, tw_ = tl & 7;

        float2 d[4][4];
#pragma unroll
        for (int i = 0; i < 4; i++)
#pragma unroll
            for (int j = 0; j < 4; j++) {
                uint32_t h2 = *(const uint32_t*)(dsm +
                    (((dtt * 10 + 2 * th_ + i) * 18 + 2 * tw_ + j) * 16
                     + cp * 2) * 2);
                d[i][j] = __half22float2(*(const __half2*)&h2);
            }
        float2 tr[4][4];
#pragma unroll
        for (int j = 0; j < 4; j++) {
            tr[0][j] = f2sub(d[0][j], d[2][j]);
            tr[1][j] = f2add(d[1][j], d[2][j]);
            tr[2][j] = f2sub(d[2][j], d[1][j]);
            tr[3][j] = f2sub(d[1][j], d[3][j]);
        }
#pragma unroll
        for (int i = 0; i < 4; i++) {
            float2 v0 = f2sub(tr[i][0], tr[i][2]);
            float2 v1 = f2add(tr[i][1], tr[i][2]);
            float2 v2 = f2sub(tr[i][2], tr[i][1]);
            float2 v3 = f2sub(tr[i][1], tr[i][3]);
            float2 vv[4] = {v0, v1, v2, v3};
#pragma unroll
            for (int j = 0; j < 4; j++) {
                __half2 hv = __float22half2_rn(vv[j]);
                *(__half2*)(dsm + VS_OFF + ((i * 4 + j) * 32 + tl) * VROW
                            + dtt * 32 + cp * 4) = hv;
            }
        }
    }

    // ---- Y accumulators: [mb][ti][par][py][px], init with bias ----
    float y[2][2][2][2][2];
    {
        const int q = lid & 3;
#pragma unroll
        for (int par = 0; par < 2; par++) {
            float bv = cbs[wid * 8 + q * 2 + par];
#pragma unroll
            for (int mb = 0; mb < 2; mb++)
#pragma unroll
                for (int ti = 0; ti < 2; ti++) {
                    y[mb][ti][par][0][0] = bv; y[mb][ti][par][0][1] = bv;
                    y[mb][ti][par][1][0] = bv; y[mb][ti][par][1][1] = bv;
                }
        }
    }
    __syncthreads();   // V^ fully built; loop below is barrier-free

    // A fragment lane addresses (LDSM from V^), two m16 tiles
    const int aRow  = (lid & 7) + 8 * ((lid >> 3) & 1);
    const int aKoff = ((lid >> 4) & 1) * 16;
    const uint32_t laneA0 = sbase + VS_OFF
        + (uint32_t)(aRow * VROW + aKoff);

    // B fragment lane gmem pointer: n = wid*8 + lid>>2, k = (lid&3)*2 (+8 for b1)
    const __half* wrow = g_wW + (size_t)(wid * 8 + (lid >> 2)) * 48
                       + (lid & 3) * 2;

    const int AT[2][4] = {{1, 1, 1, 0}, {0, 1, -1, -1}};

#pragma unroll
    for (int pt = 0; pt < 16; pt++) {
        // B fragments for this pt (L2-resident; occ-3 warps hide latency)
        uint32_t bc[6];
        {
            const __half* wp = wrow + (size_t)pt * NOC * 48;
#pragma unroll
            for (int kk = 0; kk < 3; kk++) {
                bc[2 * kk]     = __ldg((const uint32_t*)(wp + kk * 16));
                bc[2 * kk + 1] = __ldg((const uint32_t*)(wp + kk * 16 + 8));
            }
        }

        const uint32_t off = (uint32_t)(pt * 32 * VROW);
        const int xi = pt >> 2, nu = pt & 3;

#pragma unroll
        for (int mb = 0; mb < 2; mb++) {
            float c[4];
            c[0] = 0.f; c[1] = 0.f; c[2] = 0.f; c[3] = 0.f;
            const uint32_t va = laneA0 + off + (uint32_t)(mb * 16 * VROW);
#pragma unroll
            for (int kk = 0; kk < 3; kk++) {
                uint32_t a0, a1, a2, a3;
                LDSM_X4(a0, a1, a2, a3, va + kk * 32);
                MMA_F16(c, a0, a1, a2, a3, bc[2 * kk], bc[2 * kk + 1]);
            }
            // accumulate into Y with A^T coeffs (compile-time after unroll)
#pragma unroll
            for (int ti = 0; ti < 2; ti++)
#pragma unroll
                for (int par = 0; par < 2; par++) {
                    float v = c[par + 2 * ti];
#pragma unroll
                    for (int py = 0; py < 2; py++) {
                        int ay = AT[py][xi];
                        if (ay == 0) continue;
#pragma unroll
                        for (int px = 0; px < 2; px++) {
                            int ax = AT[px][nu];
                            if (ax == 0) continue;
                            if (ay * ax > 0) y[mb][ti][par][py][px] += v;
                            else            y[mb][ti][par][py][px] -= v;
                        }
                    }
                }
        }
    }

    // ---- epilogue: activate + store 2x2 px per (tile, oc) ----
    {
        const int r = lid >> 2, q = lid & 3;
        const int g  = wid >> 1;               // gate = (wid*8)>>4
        const bool th = (g == 0) || (g == 5);
        const size_t tbase = (size_t)t * HWSZ;
#pragma unroll
        for (int mb = 0; mb < 2; mb++)
#pragma unroll
            for (int ti = 0; ti < 2; ti++) {
                const int tl  = mb * 16 + r + 8 * ti;
                const int hA  = h0 + 2 * (tl >> 3);
                const int wA  = w0 + 2 * (tl & 7);
#pragma unroll
                for (int par = 0; par < 2; par++) {
                    const int oc = wid * 8 + q * 2 + par;
                    float* bp = g_gates
                        + ((size_t)(g * BB + b) * CG + (oc & 15)) * (TT * HWSZ)
                        + tbase;
#pragma unroll
                    for (int py = 0; py < 2; py++) {
                        float v0 = y[mb][ti][par][py][0];
                        float v1 = y[mb][ti][par][py][1];
                        v0 = th ? tanhfst(v0) : sigf(v0);
                        v1 = th ? tanhfst(v1) : sigf(v1);
                        *(float2*)(bp + (size_t)(hA + py) * WW + wA)
                            = make_float2(v0, v1);
                    }
                }
            }
    }
}

// ---------------- SRU scan (HBM-bound @80%, unchanged) ----------------
__global__ __launch_bounds__(256)
void sru_scan_kernel(float* __restrict__ out)
{
    const int tid = blockIdx.x * blockDim.x + threadIdx.x;
    const int hw = tid & (HWSZ - 1);
    const int bc = tid >> 14;
    const int c  = bc & 15;
    const int b  = bc >> 4;

    const size_t GSZ  = (size_t)BB * CG * TT * HWSZ;
    const size_t base = (((size_t)b * CG + c) * TT) * HWSZ + hw;

    const float* WX  = g_gates + 0 * GSZ + base;
    const float* FT  = g_gates + 1 * GSZ + base;
    const float* FT2 = g_gates + 2 * GSZ + base;
    const float* RT  = g_gates + 3 * GSZ + base;
    const float* RT2 = g_gates + 4 * GSZ + base;
    const float* XX  = g_gates + 5 * GSZ + base;
    float* o = out + base;

    float htl[TT];
    {
        float f = FT[0];
        float C = 1.0f - f;
        float r = RT[0];
        htl[0] = r * C + (1.0f - r) * XX[0];
#pragma unroll
        for (int t = 1; t < TT; t++) {
            size_t idx = (size_t)t * HWSZ;
            f = FT[idx];
            C = f * C + (1.0f - f) * WX[idx];
            float r2 = RT[idx];
            htl[t] = r2 * C + (1.0f - r2) * XX[idx];
        }
    }
    {
        size_t idx = (size_t)(TT - 1) * HWSZ;
        float f = FT2[idx];
        float C = 1.0f - f;
        float r = RT2[idx];
        o[idx] = htl[TT - 1] + r * C + (1.0f - r) * XX[idx];
#pragma unroll
        for (int t = TT - 2; t >= 0; t--) {
            idx = (size_t)t * HWSZ;
            f = FT2[idx];
            C = f * C + (1.0f - f) * WX[idx];
            float r2 = RT2[idx];
            o[idx] = htl[t] + r2 * C + (1.0f - r2) * XX[idx];
        }
    }
}

extern "C" void kernel_launch(void* const* d_in, const int* in_sizes, int n_in,
                              void* d_out, int out_size)
{
    const float* x  = (const float*)d_in[0];   // [2,16,31,128,128]
    const float* cw = (const float*)d_in[1];   // [96,16,3,3,3]
    const float* cb = (const float*)d_in[2];   // [96]
    float* out = (float*)d_out;

    cudaFuncSetAttribute(conv_wino, cudaFuncAttributeMaxDynamicSharedMemorySize,
                         SMEM_DYN);

    prep_w<<<(16 * NOC * 48 + 255) / 256, 256>>>(cw);

    dim3 grd(WW / 16, HH / 8, BB * TT);        // (8, 16, 62) = 7936 CTAs
    conv_wino<<<grd, NTHR, SMEM_DYN>>>(x, cb);

    int n = BB * CG * HWSZ;
    sru_scan_kernel<<<n / 256, 256>>>(out);
}

// round 16
// speedup vs baseline: 1.6124x; 1.1097x over previous
#include <cuda_runtime.h>
#include <cuda_fp16.h>
#include <math.h>
#include <stdint.h>

#define BB   2
#define CIN  16
#define NG   6
#define CG   16
#define NOC  96
#define TT   31
#define HH   128
#define WW   128
#define HWSZ (HH*WW)
#define HWH  (HWSZ/2)

// CTA: 8h x 16w output pixels = 4x8 = 32 Winograd tiles (2x2 out each)
#define NTHR 384          // 12 warps: each warp = ALL 32 tiles x 8 oc (oc = wid*8..+8)

// smem layout (dynamic):
//   halo [3dt][10][18][16ci] fp16 : 17280 B
//   V^   [16pt][32 tile][56 k]    : 57344 B (48 real k)
#define HALO_BYTES (3*10*18*16*2)
#define VS_OFF   HALO_BYTES
#define VROW     112
#define VS_BYTES (16*32*VROW)
#define SMEM_DYN (VS_OFF + VS_BYTES)   // 74624  -> 3 CTAs/SM

// gates scratch (fp16) [g][b][c][t][h][w]  (195 MB)
__device__ __half g_gates_h[(size_t)NG * BB * CG * TT * HWSZ];
// Winograd weights U = G g G^T : [pt=16][oc=96][48 k] fp16 (k = dt*16+ci)
__device__ __align__(16) __half g_wW[16 * NOC * 48];

// ---------------- helpers ----------------
__device__ __forceinline__ uint32_t smem_u32(const void* p) {
    uint32_t a;
    asm("{ .reg .u64 t; cvta.to.shared.u64 t, %1; cvt.u32.u64 %0, t; }"
        : "=r"(a) : "l"(p));
    return a;
}
__device__ __forceinline__ float ex2f(float z) {
    float r; asm("ex2.approx.f32 %0, %1;" : "=f"(r) : "f"(z)); return r;
}
__device__ __forceinline__ float rcpn(float d) {
    float r; asm("rcp.approx.f32 %0, %1;" : "=f"(r) : "f"(d));
    return r * fmaf(-d, r, 2.0f);
}
__device__ __forceinline__ float sigf(float v) {
    v = fminf(fmaxf(v, -80.f), 80.f);
    return rcpn(1.0f + ex2f(-1.442695041f * v));
}
__device__ __forceinline__ float tanhfst(float v) {
    v = fminf(fmaxf(v, -40.f), 40.f);
    return fmaf(2.0f, rcpn(1.0f + ex2f(-2.885390082f * v)), -1.0f);
}
__device__ __forceinline__ float2 f2add(float2 a, float2 b) {
    return make_float2(a.x + b.x, a.y + b.y);
}
__device__ __forceinline__ float2 f2sub(float2 a, float2 b) {
    return make_float2(a.x - b.x, a.y - b.y);
}

#define MMA_F16(c, a0, a1, a2, a3, b0, b1)                                    \
    asm volatile("mma.sync.aligned.m16n8k16.row.col.f32.f16.f16.f32 "         \
                 "{%0,%1,%2,%3}, {%4,%5,%6,%7}, {%8,%9}, {%0,%1,%2,%3};"      \
                 : "+f"((c)[0]), "+f"((c)[1]), "+f"((c)[2]), "+f"((c)[3])     \
                 : "r"(a0), "r"(a1), "r"(a2), "r"(a3), "r"(b0), "r"(b1))

#define LDSM_X4(r0, r1, r2, r3, addr)                                         \
    asm volatile("ldmatrix.sync.aligned.m8n8.x4.shared.b16 {%0,%1,%2,%3}, [%4];" \
                 : "=r"(r0), "=r"(r1), "=r"(r2), "=r"(r3) : "r"(addr))

// ---------------- weight prep: U = G g G^T, fp16, [pt][oc][48] ----------------
__global__ void prep_w(const float* __restrict__ cw)
{
    int idx = blockIdx.x * 256 + threadIdx.x;        // [0, 16*96*48)
    if (idx >= 16 * NOC * 48) return;
    int k  = idx % 48;
    int oc = (idx / 48) % NOC;
    int pt = idx / (48 * NOC);
    int ci = k & 15, dt = k >> 4;
    int xi = pt >> 2, nu = pt & 3;

    const float Gm[4][3] = {{1.f,0.f,0.f},{0.5f,0.5f,0.5f},
                            {0.5f,-0.5f,0.5f},{0.f,0.f,1.f}};
    const float* g = cw + ((size_t)oc * CIN + ci) * 27 + dt * 9;
    float u = 0.f;
#pragma unroll
    for (int dh = 0; dh < 3; dh++)
#pragma unroll
        for (int dw = 0; dw < 3; dw++)
            u += Gm[xi][dh] * Gm[nu][dw] * g[dh * 3 + dw];
    g_wW[((size_t)pt * NOC + oc) * 48 + k] = __float2half_rn(u);
}

// ---------------- conv: Winograd F(2x2,3x3), M32xN8 warps, occ 3 -----------
__global__ __launch_bounds__(NTHR, 3)
void conv_wino(const float* __restrict__ x, const float* __restrict__ cb)
{
    extern __shared__ __align__(16) char dsm[];
    __shared__ float cbs[NOC];

    const int tid = threadIdx.x;
    const int wid = tid >> 5;         // 0..11: oc slice = wid*8..wid*8+7
    const int lid = tid & 31;

    const int w0 = blockIdx.x * 16;
    const int h0 = blockIdx.y * 8;
    const int zz = blockIdx.z;
    const int t = zz % TT, b = zz / TT;

    const uint32_t sbase = smem_u32(dsm);

    if (tid < NOC) cbs[tid] = __ldg(&cb[tid]);

    // ---- stage halo [3][10][18][16] fp16 (h0-1..h0+8, w0-1..w0+16) ----
    {
        const float* xb = x + (size_t)b * CIN * TT * HWSZ;
        for (int i = tid; i < 3 * 10 * 18 * CIN; i += NTHR) {
            int iw  = i % 18;
            int ih  = (i / 18) % 10;
            int ci  = (i / 180) % CIN;
            int dtt = i / 2880;
            int tg = t - 1 + dtt, hh = h0 - 1 + ih, ww = w0 - 1 + iw;
            float v = 0.0f;
            if ((unsigned)tg < TT && (unsigned)hh < HH && (unsigned)ww < WW)
                v = xb[((size_t)ci * TT + tg) * HWSZ + hh * WW + ww];
            *(__half*)(dsm + (((dtt * 10 + ih) * 18 + iw) * 16 + ci) * 2)
                = __float2half_rn(v);
        }
    }
    __syncthreads();

    // ---- input transform: V^[pt][tile][k], f32 math ----
#pragma unroll
    for (int rep = 0; rep < 2; rep++) {
        const int it  = tid + rep * NTHR;
        const int cp  = it & 7;
        const int tl  = (it >> 3) & 31;
        const int dtt = it >> 8;
        const int th_ = tl >> 3, tw_ = tl & 7;

        float2 d[4][4];
#pragma unroll
        for (int i = 0; i < 4; i++)
#pragma unroll
            for (int j = 0; j < 4; j++) {
                uint32_t h2 = *(const uint32_t*)(dsm +
                    (((dtt * 10 + 2 * th_ + i) * 18 + 2 * tw_ + j) * 16
                     + cp * 2) * 2);
                d[i][j] = __half22float2(*(const __half2*)&h2);
            }
        float2 tr[4][4];
#pragma unroll
        for (int j = 0; j < 4; j++) {
            tr[0][j] = f2sub(d[0][j], d[2][j]);
            tr[1][j] = f2add(d[1][j], d[2][j]);
            tr[2][j] = f2sub(d[2][j], d[1][j]);
            tr[3][j] = f2sub(d[1][j], d[3][j]);
        }
#pragma unroll
        for (int i = 0; i < 4; i++) {
            float2 v0 = f2sub(tr[i][0], tr[i][2]);
            float2 v1 = f2add(tr[i][1], tr[i][2]);
            float2 v2 = f2sub(tr[i][2], tr[i][1]);
            float2 v3 = f2sub(tr[i][1], tr[i][3]);
            float2 vv[4] = {v0, v1, v2, v3};
#pragma unroll
            for (int j = 0; j < 4; j++) {
                __half2 hv = __float22half2_rn(vv[j]);
                *(__half2*)(dsm + VS_OFF + ((i * 4 + j) * 32 + tl) * VROW
                            + dtt * 32 + cp * 4) = hv;
            }
        }
    }

    // ---- Y accumulators: [mb][ti][par][py][px], init with bias ----
    float y[2][2][2][2][2];
    {
        const int q = lid & 3;
#pragma unroll
        for (int par = 0; par < 2; par++) {
            float bv = cbs[wid * 8 + q * 2 + par];
#pragma unroll
            for (int mb = 0; mb < 2; mb++)
#pragma unroll
                for (int ti = 0; ti < 2; ti++) {
                    y[mb][ti][par][0][0] = bv; y[mb][ti][par][0][1] = bv;
                    y[mb][ti][par][1][0] = bv; y[mb][ti][par][1][1] = bv;
                }
        }
    }
    __syncthreads();   // V^ fully built; loop below is barrier-free

    // A fragment lane addresses (LDSM from V^), two m16 tiles
    const int aRow  = (lid & 7) + 8 * ((lid >> 3) & 1);
    const int aKoff = ((lid >> 4) & 1) * 16;
    const uint32_t laneA0 = sbase + VS_OFF
        + (uint32_t)(aRow * VROW + aKoff);

    // B fragment lane gmem pointer: n = wid*8 + lid>>2, k = (lid&3)*2 (+8 for b1)
    const __half* wrow = g_wW + (size_t)(wid * 8 + (lid >> 2)) * 48
                       + (lid & 3) * 2;

    const int AT[2][4] = {{1, 1, 1, 0}, {0, 1, -1, -1}};

#pragma unroll
    for (int pt = 0; pt < 16; pt++) {
        // B fragments for this pt (L2-resident; occ-3 warps hide latency)
        uint32_t bc[6];
        {
            const __half* wp = wrow + (size_t)pt * NOC * 48;
#pragma unroll
            for (int kk = 0; kk < 3; kk++) {
                bc[2 * kk]     = __ldg((const uint32_t*)(wp + kk * 16));
                bc[2 * kk + 1] = __ldg((const uint32_t*)(wp + kk * 16 + 8));
            }
        }

        const uint32_t off = (uint32_t)(pt * 32 * VROW);
        const int xi = pt >> 2, nu = pt & 3;

#pragma unroll
        for (int mb = 0; mb < 2; mb++) {
            float c[4];
            c[0] = 0.f; c[1] = 0.f; c[2] = 0.f; c[3] = 0.f;
            const uint32_t va = laneA0 + off + (uint32_t)(mb * 16 * VROW);
#pragma unroll
            for (int kk = 0; kk < 3; kk++) {
                uint32_t a0, a1, a2, a3;
                LDSM_X4(a0, a1, a2, a3, va + kk * 32);
                MMA_F16(c, a0, a1, a2, a3, bc[2 * kk], bc[2 * kk + 1]);
            }
            // accumulate into Y with A^T coeffs (compile-time after unroll)
#pragma unroll
            for (int ti = 0; ti < 2; ti++)
#pragma unroll
                for (int par = 0; par < 2; par++) {
                    float v = c[par + 2 * ti];
#pragma unroll
                    for (int py = 0; py < 2; py++) {
                        int ay = AT[py][xi];
                        if (ay == 0) continue;
#pragma unroll
                        for (int px = 0; px < 2; px++) {
                            int ax = AT[px][nu];
                            if (ax == 0) continue;
                            if (ay * ax > 0) y[mb][ti][par][py][px] += v;
                            else            y[mb][ti][par][py][px] -= v;
                        }
                    }
                }
        }
    }

    // ---- epilogue: activate + store 2x2 px per (tile, oc), fp16 half2 ----
    {
        const int r = lid >> 2, q = lid & 3;
        const int g  = wid >> 1;               // gate = (wid*8)>>4
        const bool th = (g == 0) || (g == 5);
        const size_t tbase = (size_t)t * HWSZ;
#pragma unroll
        for (int mb = 0; mb < 2; mb++)
#pragma unroll
            for (int ti = 0; ti < 2; ti++) {
                const int tl  = mb * 16 + r + 8 * ti;
                const int hA  = h0 + 2 * (tl >> 3);
                const int wA  = w0 + 2 * (tl & 7);
#pragma unroll
                for (int par = 0; par < 2; par++) {
                    const int oc = wid * 8 + q * 2 + par;
                    __half* bp = g_gates_h
                        + ((size_t)(g * BB + b) * CG + (oc & 15)) * (TT * HWSZ)
                        + tbase;
#pragma unroll
                    for (int py = 0; py < 2; py++) {
                        float v0 = y[mb][ti][par][py][0];
                        float v1 = y[mb][ti][par][py][1];
                        v0 = th ? tanhfst(v0) : sigf(v0);
                        v1 = th ? tanhfst(v1) : sigf(v1);
                        *(__half2*)(bp + (size_t)(hA + py) * WW + wA)
                            = __floats2half2_rn(v0, v1);
                    }
                }
            }
    }
}

// ---------------- SRU scan: fp16 gates in, fp32 out, 2 px per thread -------
__global__ __launch_bounds__(256)
void sru_scan_kernel(float* __restrict__ out)
{
    const int tid = blockIdx.x * blockDim.x + threadIdx.x;   // over B*CG*HWH
    const int hwp = tid & (HWH - 1);       // HWH = 8192 = 2^13
    const int bc = tid >> 13;
    const int c  = bc & 15;
    const int b  = bc >> 4;

    const size_t GSZ  = (size_t)BB * CG * TT * HWSZ;         // in halves
    const size_t base = (((size_t)b * CG + c) * TT) * HWSZ + (size_t)hwp * 2;

    const __half2* WX  = (const __half2*)(g_gates_h + 0 * GSZ + base);
    const __half2* FT  = (const __half2*)(g_gates_h + 1 * GSZ + base);
    const __half2* FT2 = (const __half2*)(g_gates_h + 2 * GSZ + base);
    const __half2* RT  = (const __half2*)(g_gates_h + 3 * GSZ + base);
    const __half2* RT2 = (const __half2*)(g_gates_h + 4 * GSZ + base);
    const __half2* XX  = (const __half2*)(g_gates_h + 5 * GSZ + base);
    float* o = out + base;

    float2 htl[TT];
    // forward pass (ft, rt):  C0 = 1 - f0
    {
        float2 f = __half22float2(FT[0]);
        float2 xv = __half22float2(XX[0]);
        float2 r = __half22float2(RT[0]);
        float2 C = make_float2(1.f - f.x, 1.f - f.y);
        htl[0] = make_float2(r.x * C.x + (1.f - r.x) * xv.x,
                             r.y * C.y + (1.f - r.y) * xv.y);
#pragma unroll
        for (int t = 1; t < TT; t++) {
            size_t i2 = (size_t)t * HWH;
            f  = __half22float2(FT[i2]);
            float2 wv = __half22float2(WX[i2]);
            C.x = f.x * C.x + (1.f - f.x) * wv.x;
            C.y = f.y * C.y + (1.f - f.y) * wv.y;
            float2 r2 = __half22float2(RT[i2]);
            xv = __half22float2(XX[i2]);
            htl[t] = make_float2(r2.x * C.x + (1.f - r2.x) * xv.x,
                                 r2.y * C.y + (1.f - r2.y) * xv.y);
        }
    }
    // backward pass (ft2, rt2), fused add + store
    {
        size_t i2 = (size_t)(TT - 1) * HWH;
        float2 f = __half22float2(FT2[i2]);
        float2 xv = __half22float2(XX[i2]);
        float2 r = __half22float2(RT2[i2]);
        float2 C = make_float2(1.f - f.x, 1.f - f.y);
        *(float2*)(o + i2 * 2) = make_float2(
            htl[TT - 1].x + r.x * C.x + (1.f - r.x) * xv.x,
            htl[TT - 1].y + r.y * C.y + (1.f - r.y) * xv.y);
#pragma unroll
        for (int t = TT - 2; t >= 0; t--) {
            i2 = (size_t)t * HWH;
            f = __half22float2(FT2[i2]);
            float2 wv = __half22float2(WX[i2]);
            C.x = f.x * C.x + (1.f - f.x) * wv.x;
            C.y = f.y * C.y + (1.f - f.y) * wv.y;
            float2 r2 = __half22float2(RT2[i2]);
            xv = __half22float2(XX[i2]);
            *(float2*)(o + i2 * 2) = make_float2(
                htl[t].x + r2.x * C.x + (1.f - r2.x) * xv.x,
                htl[t].y + r2.y * C.y + (1.f - r2.y) * xv.y);
        }
    }
}

extern "C" void kernel_launch(void* const* d_in, const int* in_sizes, int n_in,
                              void* d_out, int out_size)
{
    const float* x  = (const float*)d_in[0];   // [2,16,31,128,128]
    const float* cw = (const float*)d_in[1];   // [96,16,3,3,3]
    const float* cb = (const float*)d_in[2];   // [96]
    float* out = (float*)d_out;

    cudaFuncSetAttribute(conv_wino, cudaFuncAttributeMaxDynamicSharedMemorySize,
                         SMEM_DYN);

    prep_w<<<(16 * NOC * 48 + 255) / 256, 256>>>(cw);

    dim3 grd(WW / 16, HH / 8, BB * TT);        // (8, 16, 62) = 7936 CTAs
    conv_wino<<<grd, NTHR, SMEM_DYN>>>(x, cb);

    int n = BB * CG * HWH;                     // 262144 threads
    sru_scan_kernel<<<n / 256, 256>>>(out);
}

// round 17
// speedup vs baseline: 1.6289x; 1.0102x over previous
#include <cuda_runtime.h>
#include <cuda_fp16.h>
#include <math.h>
#include <stdint.h>

#define BB   2
#define CIN  16
#define NG   6
#define CG   16
#define NOC  96
#define TT   31
#define HH   128
#define WW   128
#define HWSZ (HH*WW)
#define HWH  (HWSZ/2)

// CTA: 8h x 16w output pixels = 4x8 = 32 Winograd tiles (2x2 out each)
#define NTHR 384          // 12 warps: each warp = ALL 32 tiles x 8 oc

// smem: V^ ONLY (halo overlaid into the same bytes during the prologue)
//   halo [3dt][10][18][16ci] fp16 : 17280 B   (lives at offset 0, then dies)
//   V^   [16pt][32 tile][56 k]    : 57344 B   (48 real k)
#define VROW     112
#define VS_BYTES (16*32*VROW)
#define SMEM_DYN VS_BYTES              // 57344 -> 3 CTAs/SM, L1D ~55KB

// gates scratch (fp16) [g][b][c][t][h][w]  (195 MB)
__device__ __half g_gates_h[(size_t)NG * BB * CG * TT * HWSZ];
// Winograd weights, fragment-packed: [g9=oc/8][pt][lane][8 words (6 used)]
__device__ __align__(16) uint32_t g_wB[12 * 16 * 32 * 8];

// ---------------- helpers ----------------
__device__ __forceinline__ uint32_t smem_u32(const void* p) {
    uint32_t a;
    asm("{ .reg .u64 t; cvta.to.shared.u64 t, %1; cvt.u32.u64 %0, t; }"
        : "=r"(a) : "l"(p));
    return a;
}
__device__ __forceinline__ float ex2f(float z) {
    float r; asm("ex2.approx.f32 %0, %1;" : "=f"(r) : "f"(z)); return r;
}
__device__ __forceinline__ float rcpn(float d) {
    float r; asm("rcp.approx.f32 %0, %1;" : "=f"(r) : "f"(d));
    return r * fmaf(-d, r, 2.0f);
}
__device__ __forceinline__ float sigf(float v) {
    v = fminf(fmaxf(v, -80.f), 80.f);
    return rcpn(1.0f + ex2f(-1.442695041f * v));
}
__device__ __forceinline__ float tanhfst(float v) {
    v = fminf(fmaxf(v, -40.f), 40.f);
    return fmaf(2.0f, rcpn(1.0f + ex2f(-2.885390082f * v)), -1.0f);
}
__device__ __forceinline__ float2 f2add(float2 a, float2 b) {
    return make_float2(a.x + b.x, a.y + b.y);
}
__device__ __forceinline__ float2 f2sub(float2 a, float2 b) {
    return make_float2(a.x - b.x, a.y - b.y);
}

#define MMA_F16(c, a0, a1, a2, a3, b0, b1)                                    \
    asm volatile("mma.sync.aligned.m16n8k16.row.col.f32.f16.f16.f32 "         \
                 "{%0,%1,%2,%3}, {%4,%5,%6,%7}, {%8,%9}, {%0,%1,%2,%3};"      \
                 : "+f"((c)[0]), "+f"((c)[1]), "+f"((c)[2]), "+f"((c)[3])     \
                 : "r"(a0), "r"(a1), "r"(a2), "r"(a3), "r"(b0), "r"(b1))

#define LDSM_X4(r0, r1, r2, r3, addr)                                         \
    asm volatile("ldmatrix.sync.aligned.m8n8.x4.shared.b16 {%0,%1,%2,%3}, [%4];" \
                 : "=r"(r0), "=r"(r1), "=r"(r2), "=r"(r3) : "r"(addr))

// ---------------- weight prep: U = G g G^T, fragment-packed ----------------
// word w (0..5): kk = w>>1, j = w&1; oc = g9*8 + (lane>>2);
// k0 = (lane&3)*2 + kk*16 + j*8; halves (k0, k0+1); k = dt*16+ci.
__global__ void prep_w(const float* __restrict__ cw)
{
    int idx = blockIdx.x * 256 + threadIdx.x;       // [0, 12*16*32*6)
    if (idx >= 12 * 16 * 32 * 6) return;
    int w    = idx % 6;
    int lane = (idx / 6) % 32;
    int pt   = (idx / 192) % 16;
    int g9   = idx / 3072;
    int kk = w >> 1, j = w & 1;
    int oc = g9 * 8 + (lane >> 2);
    int k0 = (lane & 3) * 2 + kk * 16 + j * 8;
    int xi = pt >> 2, nu = pt & 3;

    const float Gm[4][3] = {{1.f,0.f,0.f},{0.5f,0.5f,0.5f},
                            {0.5f,-0.5f,0.5f},{0.f,0.f,1.f}};
    __half h[2];
#pragma unroll
    for (int e = 0; e < 2; e++) {
        int k = k0 + e;
        int ci = k & 15, dt = k >> 4;
        const float* g = cw + ((size_t)oc * CIN + ci) * 27 + dt * 9;
        float u = 0.f;
#pragma unroll
        for (int dh = 0; dh < 3; dh++)
#pragma unroll
            for (int dw = 0; dw < 3; dw++)
                u += Gm[xi][dh] * Gm[nu][dw] * g[dh * 3 + dw];
        h[e] = __float2half_rn(u);
    }
    uint32_t packed;
    __half2 hv = __halves2half2(h[0], h[1]);
    packed = *(uint32_t*)&hv;
    g_wB[(((size_t)g9 * 16 + pt) * 32 + lane) * 8 + w] = packed;
}

// ---------------- conv: Winograd F(2x2,3x3), V^-only smem, occ 3 ----------
__global__ __launch_bounds__(NTHR, 3)
void conv_wino(const float* __restrict__ x, const float* __restrict__ cb)
{
    extern __shared__ __align__(16) char dsm[];
    __shared__ float cbs[NOC];

    const int tid = threadIdx.x;
    const int wid = tid >> 5;         // 0..11: oc slice = wid*8..wid*8+7
    const int lid = tid & 31;

    const int w0 = blockIdx.x * 16;
    const int h0 = blockIdx.y * 8;
    const int zz = blockIdx.z;
    const int t = zz % TT, b = zz / TT;

    const uint32_t sbase = smem_u32(dsm);

    if (tid < NOC) cbs[tid] = __ldg(&cb[tid]);

    // ---- stage halo [3][10][18][16] fp16 at offset 0 (transient) ----
    {
        const float* xb = x + (size_t)b * CIN * TT * HWSZ;
        for (int i = tid; i < 3 * 10 * 18 * CIN; i += NTHR) {
            int iw  = i % 18;
            int ih  = (i / 18) % 10;
            int ci  = (i / 180) % CIN;
            int dtt = i / 2880;
            int tg = t - 1 + dtt, hh = h0 - 1 + ih, ww = w0 - 1 + iw;
            float v = 0.0f;
            if ((unsigned)tg < TT && (unsigned)hh < HH && (unsigned)ww < WW)
                v = xb[((size_t)ci * TT + tg) * HWSZ + hh * WW + ww];
            *(__half*)(dsm + (((dtt * 10 + ih) * 18 + iw) * 16 + ci) * 2)
                = __float2half_rn(v);
        }
    }
    __syncthreads();

    // ---- transform, two-phase (halo bytes are overwritten by V^) ----
    // phase 1: read both items' 4x4 half2 patches into registers
    uint32_t dreg[2][16];
#pragma unroll
    for (int rep = 0; rep < 2; rep++) {
        const int it  = tid + rep * NTHR;
        const int cp  = it & 7;
        const int tl  = (it >> 3) & 31;
        const int dtt = it >> 8;
        const int th_ = tl >> 3, tw_ = tl & 7;
#pragma unroll
        for (int i = 0; i < 4; i++)
#pragma unroll
            for (int j = 0; j < 4; j++)
                dreg[rep][i * 4 + j] = *(const uint32_t*)(dsm +
                    (((dtt * 10 + 2 * th_ + i) * 18 + 2 * tw_ + j) * 16
                     + cp * 2) * 2);
    }
    __syncthreads();   // ALL reads done before ANY V^ writes

    // phase 2: compute B^T d B in f32 and write V^[pt][tile][k] at offset 0
#pragma unroll
    for (int rep = 0; rep < 2; rep++) {
        const int it  = tid + rep * NTHR;
        const int cp  = it & 7;
        const int tl  = (it >> 3) & 31;
        const int dtt = it >> 8;

        float2 d[4][4];
#pragma unroll
        for (int i = 0; i < 4; i++)
#pragma unroll
            for (int j = 0; j < 4; j++)
                d[i][j] = __half22float2(*(const __half2*)&dreg[rep][i * 4 + j]);

        float2 tr[4][4];
#pragma unroll
        for (int j = 0; j < 4; j++) {
            tr[0][j] = f2sub(d[0][j], d[2][j]);
            tr[1][j] = f2add(d[1][j], d[2][j]);
            tr[2][j] = f2sub(d[2][j], d[1][j]);
            tr[3][j] = f2sub(d[1][j], d[3][j]);
        }
#pragma unroll
        for (int i = 0; i < 4; i++) {
            float2 v0 = f2sub(tr[i][0], tr[i][2]);
            float2 v1 = f2add(tr[i][1], tr[i][2]);
            float2 v2 = f2sub(tr[i][2], tr[i][1]);
            float2 v3 = f2sub(tr[i][1], tr[i][3]);
            float2 vv[4] = {v0, v1, v2, v3};
#pragma unroll
            for (int j = 0; j < 4; j++) {
                __half2 hv = __float22half2_rn(vv[j]);
                *(__half2*)(dsm + ((i * 4 + j) * 32 + tl) * VROW
                            + dtt * 32 + cp * 4) = hv;
            }
        }
    }

    // ---- Y accumulators: [mb][ti][par][py][px], init with bias ----
    float y[2][2][2][2][2];
    {
        const int q = lid & 3;
#pragma unroll
        for (int par = 0; par < 2; par++) {
            float bv = cbs[wid * 8 + q * 2 + par];
#pragma unroll
            for (int mb = 0; mb < 2; mb++)
#pragma unroll
                for (int ti = 0; ti < 2; ti++) {
                    y[mb][ti][par][0][0] = bv; y[mb][ti][par][0][1] = bv;
                    y[mb][ti][par][1][0] = bv; y[mb][ti][par][1][1] = bv;
                }
        }
    }
    __syncthreads();   // V^ fully built; loop below is barrier-free

    // A fragment lane addresses (LDSM from V^ at offset 0)
    const int aRow  = (lid & 7) + 8 * ((lid >> 3) & 1);
    const int aKoff = ((lid >> 4) & 1) * 16;
    const uint32_t laneA0 = sbase + (uint32_t)(aRow * VROW + aKoff);

    // B fragment gmem pointer: packed [wid][pt][lid][8 words]
    const uint4* wlane = (const uint4*)(g_wB + (((size_t)wid * 16) * 32 + lid) * 8);

    const int AT[2][4] = {{1, 1, 1, 0}, {0, 1, -1, -1}};

#pragma unroll
    for (int pt = 0; pt < 16; pt++) {
        // B fragments: one LDG.128 + one LDG.64 (L1-resident)
        uint32_t bc[6];
        {
            const uint4* wp = wlane + (size_t)pt * 64;   // 32 lanes * 2 uint4
            uint4 B0 = __ldg(wp);
            uint2 B1 = __ldg((const uint2*)(wp + 1));
            bc[0] = B0.x; bc[1] = B0.y; bc[2] = B0.z;
            bc[3] = B0.w; bc[4] = B1.x; bc[5] = B1.y;
        }

        const uint32_t off = (uint32_t)(pt * 32 * VROW);
        const int xi = pt >> 2, nu = pt & 3;

#pragma unroll
        for (int mb = 0; mb < 2; mb++) {
            float c[4];
            c[0] = 0.f; c[1] = 0.f; c[2] = 0.f; c[3] = 0.f;
            const uint32_t va = laneA0 + off + (uint32_t)(mb * 16 * VROW);
#pragma unroll
            for (int kk = 0; kk < 3; kk++) {
                uint32_t a0, a1, a2, a3;
                LDSM_X4(a0, a1, a2, a3, va + kk * 32);
                MMA_F16(c, a0, a1, a2, a3, bc[2 * kk], bc[2 * kk + 1]);
            }
            // accumulate into Y with A^T coeffs (compile-time after unroll)
#pragma unroll
            for (int ti = 0; ti < 2; ti++)
#pragma unroll
                for (int par = 0; par < 2; par++) {
                    float v = c[par + 2 * ti];
#pragma unroll
                    for (int py = 0; py < 2; py++) {
                        int ay = AT[py][xi];
                        if (ay == 0) continue;
#pragma unroll
                        for (int px = 0; px < 2; px++) {
                            int ax = AT[px][nu];
                            if (ax == 0) continue;
                            if (ay * ax > 0) y[mb][ti][par][py][px] += v;
                            else            y[mb][ti][par][py][px] -= v;
                        }
                    }
                }
        }
    }

    // ---- epilogue: activate + store 2x2 px per (tile, oc), fp16 half2 ----
    {
        const int r = lid >> 2, q = lid & 3;
        const int g  = wid >> 1;               // gate = (wid*8)>>4
        const bool th = (g == 0) || (g == 5);
        const size_t tbase = (size_t)t * HWSZ;
#pragma unroll
        for (int mb = 0; mb < 2; mb++)
#pragma unroll
            for (int ti = 0; ti < 2; ti++) {
                const int tl  = mb * 16 + r + 8 * ti;
                const int hA  = h0 + 2 * (tl >> 3);
                const int wA  = w0 + 2 * (tl & 7);
#pragma unroll
                for (int par = 0; par < 2; par++) {
                    const int oc = wid * 8 + q * 2 + par;
                    __half* bp = g_gates_h
                        + ((size_t)(g * BB + b) * CG + (oc & 15)) * (TT * HWSZ)
                        + tbase;
#pragma unroll
                    for (int py = 0; py < 2; py++) {
                        float v0 = y[mb][ti][par][py][0];
                        float v1 = y[mb][ti][par][py][1];
                        v0 = th ? tanhfst(v0) : sigf(v0);
                        v1 = th ? tanhfst(v1) : sigf(v1);
                        *(__half2*)(bp + (size_t)(hA + py) * WW + wA)
                            = __floats2half2_rn(v0, v1);
                    }
                }
            }
    }
}

// ---------------- SRU scan: fp16 gates in, fp32 out, 2 px per thread -------
__global__ __launch_bounds__(256)
void sru_scan_kernel(float* __restrict__ out)
{
    const int tid = blockIdx.x * blockDim.x + threadIdx.x;   // over B*CG*HWH
    const int hwp = tid & (HWH - 1);       // HWH = 8192 = 2^13
    const int bc = tid >> 13;
    const int c  = bc & 15;
    const int b  = bc >> 4;

    const size_t GSZ  = (size_t)BB * CG * TT * HWSZ;         // in halves
    const size_t base = (((size_t)b * CG + c) * TT) * HWSZ + (size_t)hwp * 2;

    const __half2* WX  = (const __half2*)(g_gates_h + 0 * GSZ + base);
    const __half2* FT  = (const __half2*)(g_gates_h + 1 * GSZ + base);
    const __half2* FT2 = (const __half2*)(g_gates_h + 2 * GSZ + base);
    const __half2* RT  = (const __half2*)(g_gates_h + 3 * GSZ + base);
    const __half2* RT2 = (const __half2*)(g_gates_h + 4 * GSZ + base);
    const __half2* XX  = (const __half2*)(g_gates_h + 5 * GSZ + base);
    float* o = out + base;

    float2 htl[TT];
    // forward pass (ft, rt):  C0 = 1 - f0
    {
        float2 f = __half22float2(FT[0]);
        float2 xv = __half22float2(XX[0]);
        float2 r = __half22float2(RT[0]);
        float2 C = make_float2(1.f - f.x, 1.f - f.y);
        htl[0] = make_float2(r.x * C.x + (1.f - r.x) * xv.x,
                             r.y * C.y + (1.f - r.y) * xv.y);
#pragma unroll
        for (int t = 1; t < TT; t++) {
            size_t i2 = (size_t)t * HWH;
            f  = __half22float2(FT[i2]);
            float2 wv = __half22float2(WX[i2]);
            C.x = f.x * C.x + (1.f - f.x) * wv.x;
            C.y = f.y * C.y + (1.f - f.y) * wv.y;
            float2 r2 = __half22float2(RT[i2]);
            xv = __half22float2(XX[i2]);
            htl[t] = make_float2(r2.x * C.x + (1.f - r2.x) * xv.x,
                                 r2.y * C.y + (1.f - r2.y) * xv.y);
        }
    }
    // backward pass (ft2, rt2), fused add + store
    {
        size_t i2 = (size_t)(TT - 1) * HWH;
        float2 f = __half22float2(FT2[i2]);
        float2 xv = __half22float2(XX[i2]);
        float2 r = __half22float2(RT2[i2]);
        float2 C = make_float2(1.f - f.x, 1.f - f.y);
        *(float2*)(o + i2 * 2) = make_float2(
            htl[TT - 1].x + r.x * C.x + (1.f - r.x) * xv.x,
            htl[TT - 1].y + r.y * C.y + (1.f - r.y) * xv.y);
#pragma unroll
        for (int t = TT - 2; t >= 0; t--) {
            i2 = (size_t)t * HWH;
            f = __half22float2(FT2[i2]);
            float2 wv = __half22float2(WX[i2]);
            C.x = f.x * C.x + (1.f - f.x) * wv.x;
            C.y = f.y * C.y + (1.f - f.y) * wv.y;
            float2 r2 = __half22float2(RT2[i2]);
            xv = __half22float2(XX[i2]);
            *(float2*)(o + i2 * 2) = make_float2(
                htl[t].x + r2.x * C.x + (1.f - r2.x) * xv.x,
                htl[t].y + r2.y * C.y + (1.f - r2.y) * xv.y);
        }
    }
}

extern "C" void kernel_launch(void* const* d_in, const int* in_sizes, int n_in,
                              void* d_out, int out_size)
{
    const float* x  = (const float*)d_in[0];   // [2,16,31,128,128]
    const float* cw = (const float*)d_in[1];   // [96,16,3,3,3]
    const float* cb = (const float*)d_in[2];   // [96]
    float* out = (float*)d_out;

    cudaFuncSetAttribute(conv_wino, cudaFuncAttributeMaxDynamicSharedMemorySize,
                         SMEM_DYN);
    cudaFuncSetAttribute(conv_wino, cudaFuncAttributePreferredSharedMemoryCarveout,
                         75);   // ~172KB smem, leave rest as L1

    prep_w<<<(12 * 16 * 32 * 6 + 255) / 256, 256>>>(cw);

    dim3 grd(WW / 16, HH / 8, BB * TT);        // (8, 16, 62) = 7936 CTAs
    conv_wino<<<grd, NTHR, SMEM_DYN>>>(x, cb);

    int n = BB * CG * HWH;                     // 262144 threads
    sru_scan_kernel<<<n / 256, 256>>>(out);
}